// round 15
// baseline (speedup 1.0000x reference)
#include <cuda_runtime.h>
#include <cuda_fp16.h>
#include <cstdint>
#include <cstddef>

#define DEV_INLINE __device__ __forceinline__

constexpr int B_  = 32;
constexpr int T_  = 1500;
constexpr int A_  = 512;
constexpr int E_  = 512;
constexpr int H_  = 512;
constexpr int V_  = 10000;
constexpr int LQ  = 101;    // L+1
constexpr int G4H = 2048;   // 4*H
constexpr int NCK = 12;     // fused attn/context T-chunks (strided assignment)
constexpr int MPAD = 3328;  // 26*128 (rows padded)
constexpr int NPAD = 10112; // 79*128 (vocab padded)

// ---------------- device scratch (static, allowed) ----------------
__device__ __half g_PX[(size_t)B_ * T_ * 1024];      // row t: [P(512) | X(512)] fp16 (98 MB)
__device__ __half g_embH[(size_t)MPAD * E_];         // gathered embeddings fp16, padded
__device__ __half g_WihH[(size_t)G4H * 512];         // W_ih[:, :512] fp16
__device__ float g_embg[(size_t)B_ * LQ * G4H];      // emb-part of gates + bias
__device__ __half g_zcH[(size_t)MPAD * 1024];        // [dec_z | c] fp16, padded (pad rows stay 0)
__device__ __half g_WoutH[(size_t)NPAD * 1024];      // W_out fp16, padded
__device__ __half g_WencHT[A_ * A_];                 // W_enc^T in fp16
__device__ __half g_WdecH[(size_t)H_ * A_];          // W_dec fp16 [k][j]
__device__ __half g_WrecH[(size_t)G4H * 1024];       // [W_ih(:,512:1024) | W_hh] fp16
__device__ float g_bias[G4H];                        // b_ih + b_hh
__device__ float g_decz[B_ * H_];
__device__ float g_decc[B_ * H_];
__device__ float g_q[B_ * A_];
__device__ float g_gpart[8 * B_ * G4H];              // split-K partials of gates
__device__ float g_ueA[(size_t)B_ * LQ * T_];        // exp(e) for ALL steps (19.4 MB)
__device__ float g_epartA[(size_t)B_ * LQ * NCK];    // per-chunk ue sums, all steps
__device__ float g_cpart[(size_t)NCK * B_ * A_];     // UNNORMALIZED context partials

// ---------------- helpers ----------------
DEV_INLINE unsigned long long pack2(float x, float y) {
    unsigned long long r;
    asm("mov.b64 %0, {%1, %2};" : "=l"(r) : "f"(x), "f"(y));
    return r;
}
DEV_INLINE void ffma2(unsigned long long& acc, unsigned long long a2, unsigned long long b2) {
    asm("fma.rn.f32x2 %0, %1, %2, %0;" : "+l"(acc) : "l"(a2), "l"(b2));
}
DEV_INLINE float lo32(unsigned long long v) { return __uint_as_float((unsigned)(v & 0xffffffffull)); }
DEV_INLINE float hi32(unsigned long long v) { return __uint_as_float((unsigned)(v >> 32)); }

DEV_INLINE float tanh_mufu(float x) {
    float y;
    asm("tanh.approx.f32 %0, %1;" : "=f"(y) : "f"(x));
    return y;
}
DEV_INLINE float sig_acc(float x) { return 1.f / (1.f + expf(-x)); }

DEV_INLINE void stcs_f(float* p, float v) {
    asm volatile("st.global.cs.f32 [%0], %1;" :: "l"(p), "f"(v) : "memory");
}

#define LDMATRIX_X4(R0, R1, R2, R3, addr)                                      \
    asm volatile("ldmatrix.sync.aligned.m8n8.x4.shared.b16 {%0,%1,%2,%3}, [%4];" \
                 : "=r"(R0), "=r"(R1), "=r"(R2), "=r"(R3) : "r"(addr))

#define MMA16816(d, a, b)                                                      \
    asm volatile("mma.sync.aligned.m16n8k16.row.col.f32.f16.f16.f32 "          \
                 "{%0,%1,%2,%3}, {%4,%5,%6,%7}, {%8,%9}, {%0,%1,%2,%3};"       \
                 : "+f"(d[0]), "+f"(d[1]), "+f"(d[2]), "+f"(d[3])              \
                 : "r"(a[0]), "r"(a[1]), "r"(a[2]), "r"(a[3]),                 \
                   "r"(b[0]), "r"(b[1]))

// ---------------- setup kernels ----------------
__global__ void init_state_kernel() {
    int i = blockIdx.x * blockDim.x + threadIdx.x;
    if (i < B_ * H_) { g_decz[i] = 0.f; g_decc[i] = 0.f; }
    if (i < NCK * B_ * A_) g_cpart[i] = 0.f;
}

// write enc_pad (fp16) into the X half of g_PX (row stride 1024 halfs)
__global__ void convert_enc_kernel(const float* __restrict__ enc) {
    size_t i = (size_t)blockIdx.x * blockDim.x + threadIdx.x;   // half2 index
    size_t n2 = (size_t)B_ * T_ * A_ / 2;
    if (i < n2) {
        float2 f = ((const float2*)enc)[i];
        size_t row = i >> 8;            // 256 half2 per 512-wide X row
        size_t cp  = i & 255;
        ((__half2*)g_PX)[row * 512 + 256 + cp] = __floats2half2_rn(f.x, f.y);
    }
}

__global__ void transpose_wenc_h_kernel(const float* __restrict__ We,
                                        const float* __restrict__ Wd) {
    int idx = blockIdx.x * 256 + threadIdx.x;
    if (idx < 512 * 512) {
        int d = idx >> 9, a = idx & 511;
        g_WencHT[a * 512 + d] = __float2half_rn(We[idx]);
        g_WdecH[idx] = __float2half_rn(Wd[idx]);
    }
}

__global__ void convert_wout_kernel(const float* __restrict__ W_out) {
    size_t idx = (size_t)blockIdx.x * 256 + threadIdx.x;
    if (idx < (size_t)NPAD * 1024) {
        int n = (int)(idx >> 10), k = (int)(idx & 1023);
        g_WoutH[idx] = (n < V_) ? __float2half_rn(W_out[(size_t)n * 1024 + k]) : __half(0);
    }
}

__global__ void pack_wrec_kernel(const float* __restrict__ W_ih, const float* __restrict__ W_hh,
                                 const float* __restrict__ b_ih, const float* __restrict__ b_hh) {
    int idx = blockIdx.x * 256 + threadIdx.x;
    if (idx < G4H * 1024) {
        int j = idx >> 10, k = idx & 1023;
        float v = (k < 512) ? W_ih[(size_t)j * 1024 + 512 + k]
                            : W_hh[(size_t)j * 512 + (k - 512)];
        g_WrecH[idx] = __float2half_rn(v);
    }
    if (idx < G4H * 512) {
        int j = idx >> 9, k = idx & 511;
        g_WihH[idx] = __float2half_rn(W_ih[(size_t)j * 1024 + k]);
    }
    if (idx < G4H) g_bias[idx] = b_ih[idx] + b_hh[idx];
}

__global__ void gather_emb_kernel(const int* __restrict__ ys, const float* __restrict__ emb) {
    int m = blockIdx.x;
    int b = m / LQ, t = m % LQ;
    int idx = (t == 0) ? 1 : ys[b * 100 + t - 1];   // BOS=1
    const float* src = &emb[(size_t)idx * 512];
    __half* dst = &g_embH[(size_t)m * 512];
    for (int k = threadIdx.x; k < 512; k += 128) dst[k] = __float2half_rn(src[k]);
}

// ---------------- HMMA tensor-core NT GEMM ----------------
DEV_INLINE void store_out(float* p, float v) { *p = v; }
DEV_INLINE void store_out(__half* p, float v) { *p = __float2half_rn(v); }

template <typename OutT>
__global__ void __launch_bounds__(256) hgemm_nt(
    const __half* __restrict__ A, int lda,
    const __half* __restrict__ Bm, int ldb,
    const float* __restrict__ bias,
    OutT* __restrict__ C, int ldc,
    int M, int N, int K)
{
    __shared__ __half As[2][128][40];
    __shared__ __half Bs[2][128][40];

    const int tid = threadIdx.x;
    const int row0 = blockIdx.y * 128, col0 = blockIdx.x * 128;
    const int warp = tid >> 5, lane = tid & 31;
    const int wm = warp & 1, wn = warp >> 1;

    const int grow = tid >> 1;
    const int gcol = (tid & 1) * 16;
    const __half* a_src = A + (size_t)(row0 + grow) * lda + gcol;
    const __half* b_src = Bm + (size_t)(col0 + grow) * ldb + gcol;

    uint4 ar0, ar1, br0, br1;
    float acc[4][4][4];
#pragma unroll
    for (int i = 0; i < 4; i++)
#pragma unroll
        for (int j = 0; j < 4; j++) {
            acc[i][j][0] = 0.f; acc[i][j][1] = 0.f; acc[i][j][2] = 0.f; acc[i][j][3] = 0.f;
        }

#define LOADG(k0)                                                              \
    do {                                                                       \
        ar0 = *(const uint4*)(a_src + (k0));                                   \
        ar1 = *(const uint4*)(a_src + (k0) + 8);                               \
        br0 = *(const uint4*)(b_src + (k0));                                   \
        br1 = *(const uint4*)(b_src + (k0) + 8);                               \
    } while (0)

#define STORES(buf)                                                            \
    do {                                                                       \
        *(uint4*)&As[buf][grow][gcol]     = ar0;                               \
        *(uint4*)&As[buf][grow][gcol + 8] = ar1;                               \
        *(uint4*)&Bs[buf][grow][gcol]     = br0;                               \
        *(uint4*)&Bs[buf][grow][gcol + 8] = br1;                               \
    } while (0)

    const int ntiles = K >> 5;
    LOADG(0);
    STORES(0);
    if (ntiles > 1) LOADG(32);
    __syncthreads();

    const int a_row = wm * 64 + (lane & 15);
    const int a_kof = (lane >> 4) * 8;
    const int b_rof = (lane & 7) + ((lane >> 4) & 1) * 8;
    const int b_kof = ((lane >> 3) & 1) * 8;

    for (int kt = 0; kt < ntiles; kt++) {
        const int cur = kt & 1;
#pragma unroll
        for (int ks = 0; ks < 2; ks++) {
            const int kc = ks * 16;
            uint32_t a_frag[4][4];
            uint32_t b_frag[4][2];
#pragma unroll
            for (int mi = 0; mi < 4; mi++) {
                uint32_t addr = (uint32_t)__cvta_generic_to_shared(
                    &As[cur][a_row + mi * 16][kc + a_kof]);
                LDMATRIX_X4(a_frag[mi][0], a_frag[mi][1], a_frag[mi][2], a_frag[mi][3], addr);
            }
#pragma unroll
            for (int p = 0; p < 2; p++) {
                uint32_t r0, r1, r2, r3;
                uint32_t addr = (uint32_t)__cvta_generic_to_shared(
                    &Bs[cur][wn * 32 + p * 16 + b_rof][kc + b_kof]);
                LDMATRIX_X4(r0, r1, r2, r3, addr);
                b_frag[p * 2][0] = r0;     b_frag[p * 2][1] = r1;
                b_frag[p * 2 + 1][0] = r2; b_frag[p * 2 + 1][1] = r3;
            }
#pragma unroll
            for (int mi = 0; mi < 4; mi++) {
#pragma unroll
                for (int nj = 0; nj < 4; nj++) {
                    MMA16816(acc[mi][nj], a_frag[mi], b_frag[nj]);
                }
            }
        }
        if (kt + 1 < ntiles) {
            STORES((kt + 1) & 1);
            if (kt + 2 < ntiles) LOADG((kt + 2) * 32);
        }
        __syncthreads();
    }
#undef LOADG
#undef STORES

#pragma unroll
    for (int mi = 0; mi < 4; mi++) {
        int r = row0 + wm * 64 + mi * 16 + (lane >> 2);
#pragma unroll
        for (int nj = 0; nj < 4; nj++) {
            int c = col0 + wn * 32 + nj * 8 + (lane & 3) * 2;
            float b0 = (bias && c < N)     ? bias[c]     : 0.f;
            float b1 = (bias && c + 1 < N) ? bias[c + 1] : 0.f;
            if (r < M) {
                OutT* crow = C + (size_t)r * ldc;
                if (c < N)     store_out(crow + c,     acc[mi][nj][0] + b0);
                if (c + 1 < N) store_out(crow + c + 1, acc[mi][nj][1] + b1);
            }
            if (r + 8 < M) {
                OutT* crow = C + (size_t)(r + 8) * ldc;
                if (c < N)     store_out(crow + c,     acc[mi][nj][2] + b0);
                if (c + 1 < N) store_out(crow + c + 1, acc[mi][nj][3] + b1);
            }
        }
    }
}

// ---------------- per-step recurrent gates (split-K, fp16 Wrec) ----------
__global__ void __launch_bounds__(256) gates_kernel(int step) {
    __shared__ float xh_s[32][36];
    __shared__ float w_s[32][132];
    __shared__ float inv_s[32];
    int tid = threadIdx.x;
    int j0 = blockIdx.x * 128;
    int kz = blockIdx.y;
    int bq = tid & 7;
    int jq = tid >> 3;

    if (tid < 32) {
        float iv = 1.f;
        if (step > 0) {
            float s = 0.f;
#pragma unroll
            for (int i = 0; i < NCK; i++)
                s += g_epartA[((size_t)tid * LQ + step - 1) * NCK + i];
            iv = 1.f / s;
        }
        inv_s[tid] = iv;
    }
    __syncthreads();

    unsigned long long acc[4][2];
#pragma unroll
    for (int i = 0; i < 4; i++) { acc[i][0] = 0ull; acc[i][1] = 0ull; }

    for (int kt0 = 0; kt0 < 128; kt0 += 32) {
        int kb = kz * 128 + kt0;
#pragma unroll
        for (int r = 0; r < 4; r++) {
            int lin = tid + r * 256;
            int kt = lin & 31, b = lin >> 5;
            int kk = kb + kt;
            float v;
            if (kk < 512) {
                v = 0.f;
#pragma unroll
                for (int tc = 0; tc < NCK; tc++)
                    v += g_cpart[((size_t)tc * B_ + b) * A_ + kk];
                v *= inv_s[b];
                if (blockIdx.x == 0 && step > 0)
                    g_zcH[((size_t)b * LQ + step - 1) * 1024 + 512 + kk] = __float2half_rn(v);
            } else {
                v = g_decz[b * 512 + kk - 512];
            }
            xh_s[kt][b] = v;
        }
        {
            int jj = tid >> 1, kof = (tid & 1) * 16;
            const __half* wp = &g_WrecH[(size_t)(j0 + jj) * 1024 + kb + kof];
            uint4 h0 = *(const uint4*)wp;
            uint4 h1 = *(const uint4*)(wp + 8);
            const __half2* p0 = (const __half2*)&h0;
            const __half2* p1 = (const __half2*)&h1;
#pragma unroll
            for (int q = 0; q < 4; q++) {
                float2 f = __half22float2(p0[q]);
                w_s[kof + 2 * q][jj]     = f.x;
                w_s[kof + 2 * q + 1][jj] = f.y;
            }
#pragma unroll
            for (int q = 0; q < 4; q++) {
                float2 f = __half22float2(p1[q]);
                w_s[kof + 8 + 2 * q][jj]     = f.x;
                w_s[kof + 8 + 2 * q + 1][jj] = f.y;
            }
        }
        __syncthreads();
#pragma unroll
        for (int kt = 0; kt < 32; kt++) {
            float4 av = *(const float4*)&xh_s[kt][bq * 4];
            float4 wv = *(const float4*)&w_s[kt][jq * 4];
            unsigned long long w2a = pack2(wv.x, wv.y);
            unsigned long long w2b = pack2(wv.z, wv.w);
            unsigned long long a2;
            a2 = pack2(av.x, av.x); ffma2(acc[0][0], a2, w2a); ffma2(acc[0][1], a2, w2b);
            a2 = pack2(av.y, av.y); ffma2(acc[1][0], a2, w2a); ffma2(acc[1][1], a2, w2b);
            a2 = pack2(av.z, av.z); ffma2(acc[2][0], a2, w2a); ffma2(acc[2][1], a2, w2b);
            a2 = pack2(av.w, av.w); ffma2(acc[3][0], a2, w2a); ffma2(acc[3][1], a2, w2b);
        }
        __syncthreads();
    }
#pragma unroll
    for (int ib = 0; ib < 4; ib++) {
        int b = bq * 4 + ib;
        float* gp = &g_gpart[(size_t)kz * (B_ * G4H) + (size_t)b * G4H + j0 + jq * 4];
        gp[0] = lo32(acc[ib][0]); gp[1] = hi32(acc[ib][0]);
        gp[2] = lo32(acc[ib][1]); gp[3] = hi32(acc[ib][1]);
    }
}

// ---------------- per-step LSTM pointwise + q GEMV (fp16 W_dec, 4-way) -----
__global__ void __launch_bounds__(1024) lstm_pw_q_kernel(int step) {
    int b = blockIdx.x;
    int tid = threadIdx.x;
    __shared__ float z_s[512];
    __shared__ float2 qp2[1024];

    if (tid < 512) {
        size_t m = (size_t)b * LQ + step;
        const float* eg = &g_embg[m * G4H];
        float gi = eg[tid], gf = eg[512 + tid], gg = eg[1024 + tid], go = eg[1536 + tid];
#pragma unroll
        for (int kz = 0; kz < 8; kz++) {
            const float* gp = &g_gpart[(size_t)kz * (B_ * G4H) + (size_t)b * G4H];
            gi += gp[tid]; gf += gp[512 + tid]; gg += gp[1024 + tid]; go += gp[1536 + tid];
        }
        float cp = g_decc[b * 512 + tid];
        float cn = sig_acc(gf) * cp + sig_acc(gi) * tanhf(gg);
        float z  = sig_acc(go) * tanhf(cn);
        g_decc[b * 512 + tid] = cn;
        g_decz[b * 512 + tid] = z;
        g_zcH[m * 1024 + tid] = __float2half_rn(z);
        z_s[tid] = z;
    }
    __syncthreads();

    int jp = tid & 255;          // half2 column pair (j = 2jp, 2jp+1)
    int k0 = tid >> 8;           // 0..3, 128 k each
    const __half2* wdh = (const __half2*)g_WdecH;
    float qx = 0.f, qy = 0.f;
#pragma unroll 8
    for (int k = 0; k < 128; k++) {
        int kk = k0 * 128 + k;
        float2 w = __half22float2(wdh[(size_t)kk * 256 + jp]);
        float zk = z_s[kk];
        qx += zk * w.x;
        qy += zk * w.y;
    }
    qp2[tid] = make_float2(qx, qy);
    __syncthreads();
    if (tid < 256) {
        float2 a = qp2[tid], b2 = qp2[tid + 256], c = qp2[tid + 512], d = qp2[tid + 768];
        g_q[b * 512 + 2 * tid]     = (a.x + b2.x) + (c.x + d.x);
        g_q[b * 512 + 2 * tid + 1] = (a.y + b2.y) + (c.y + d.y);
    }
}

// ---------------- per-step FUSED attention scores + context (strided t) ----
// Row t of g_PX is a contiguous 2 KB block: [P(512) | X(512)] fp16.
__global__ void __launch_bounds__(256) attn_ctx_kernel(const int* __restrict__ enc_len,
                                                       const float* __restrict__ v_att,
                                                       int step) {
    int b = blockIdx.y, chunk = blockIdx.x;
    int len = enc_len[b];
    int tid = threadIdx.x, warp = tid >> 5, lane = tid & 31;
    __shared__ float sacc[8][512];
    __shared__ float wred[8];

    float qv[16], vv[16];
    {
        const float* qb = &g_q[b * 512 + lane * 8];
        *(float4*)&qv[0]  = *(const float4*)(qb);
        *(float4*)&qv[4]  = *(const float4*)(qb + 4);
        *(float4*)&qv[8]  = *(const float4*)(qb + 256);
        *(float4*)&qv[12] = *(const float4*)(qb + 260);
        const float* vb = &v_att[lane * 8];
        *(float4*)&vv[0]  = *(const float4*)(vb);
        *(float4*)&vv[4]  = *(const float4*)(vb + 4);
        *(float4*)&vv[8]  = *(const float4*)(vb + 256);
        *(float4*)&vv[12] = *(const float4*)(vb + 260);
    }
    float acc[16];
#pragma unroll
    for (int i = 0; i < 16; i++) acc[i] = 0.f;

    const int iw = warp * 16;
    float wsum = 0.f;
    float* uerow = &g_ueA[((size_t)b * LQ + step) * T_];
    const __half* Rb = &g_PX[(size_t)b * T_ * 1024];

#pragma unroll 1
    for (int r = 0; r < 16; r += 2) {
        int t0 = chunk + 12 * (iw + r);
        if (t0 >= len) break;
        int t1 = t0 + 12;
        bool m1 = (t1 < len);
        uint4 z4 = make_uint4(0, 0, 0, 0);
        const __half* R0 = Rb + (size_t)t0 * 1024;
        const __half* R1 = Rb + (size_t)t1 * 1024;
        uint4 u0a = __ldcs((const uint4*)(R0 + lane * 8));
        uint4 u0b = __ldcs((const uint4*)(R0 + 256 + lane * 8));
        uint4 x0a = __ldcs((const uint4*)(R0 + 512 + lane * 8));
        uint4 x0b = __ldcs((const uint4*)(R0 + 768 + lane * 8));
        uint4 u1a = m1 ? __ldcs((const uint4*)(R1 + lane * 8))       : z4;
        uint4 u1b = m1 ? __ldcs((const uint4*)(R1 + 256 + lane * 8)) : z4;
        uint4 x1a = m1 ? __ldcs((const uint4*)(R1 + 512 + lane * 8)) : z4;
        uint4 x1b = m1 ? __ldcs((const uint4*)(R1 + 768 + lane * 8)) : z4;

        float s0 = 0.f, s1 = 0.f;
        {
            const __half2* h0a = (const __half2*)&u0a;
            const __half2* h0b = (const __half2*)&u0b;
            const __half2* h1a = (const __half2*)&u1a;
            const __half2* h1b = (const __half2*)&u1b;
#pragma unroll
            for (int j = 0; j < 4; j++) {
                float2 f0 = __half22float2(h0a[j]);
                float2 f1 = __half22float2(h1a[j]);
                s0 += vv[2*j]   * tanh_mufu(f0.x + qv[2*j]);
                s0 += vv[2*j+1] * tanh_mufu(f0.y + qv[2*j+1]);
                s1 += vv[2*j]   * tanh_mufu(f1.x + qv[2*j]);
                s1 += vv[2*j+1] * tanh_mufu(f1.y + qv[2*j+1]);
            }
#pragma unroll
            for (int j = 0; j < 4; j++) {
                float2 f0 = __half22float2(h0b[j]);
                float2 f1 = __half22float2(h1b[j]);
                s0 += vv[8+2*j]   * tanh_mufu(f0.x + qv[8+2*j]);
                s0 += vv[8+2*j+1] * tanh_mufu(f0.y + qv[8+2*j+1]);
                s1 += vv[8+2*j]   * tanh_mufu(f1.x + qv[8+2*j]);
                s1 += vv[8+2*j+1] * tanh_mufu(f1.y + qv[8+2*j+1]);
            }
        }
#pragma unroll
        for (int off = 16; off; off >>= 1) {
            s0 += __shfl_xor_sync(0xffffffffu, s0, off);
            s1 += __shfl_xor_sync(0xffffffffu, s1, off);
        }
        float ue0 = __expf(s0);
        float ue1 = m1 ? __expf(s1) : 0.f;
        if (lane == 0) {
            stcs_f(uerow + t0, ue0);
            if (m1) stcs_f(uerow + t1, ue1);
        }
        wsum += ue0 + ue1;
        {
            const __half2* g0a = (const __half2*)&x0a;
            const __half2* g0b = (const __half2*)&x0b;
            const __half2* g1a = (const __half2*)&x1a;
            const __half2* g1b = (const __half2*)&x1b;
#pragma unroll
            for (int j = 0; j < 4; j++) {
                float2 f0 = __half22float2(g0a[j]);
                float2 f1 = __half22float2(g1a[j]);
                acc[2*j]   += ue0 * f0.x + ue1 * f1.x;
                acc[2*j+1] += ue0 * f0.y + ue1 * f1.y;
            }
#pragma unroll
            for (int j = 0; j < 4; j++) {
                float2 f0 = __half22float2(g0b[j]);
                float2 f1 = __half22float2(g1b[j]);
                acc[8+2*j]   += ue0 * f0.x + ue1 * f1.x;
                acc[8+2*j+1] += ue0 * f0.y + ue1 * f1.y;
            }
        }
    }

#pragma unroll
    for (int i = 0; i < 8; i++) {
        sacc[warp][lane * 8 + i]       = acc[i];
        sacc[warp][256 + lane * 8 + i] = acc[8 + i];
    }
    if (lane == 0) wred[warp] = wsum;
    __syncthreads();

    int a0 = tid * 2;
    float r0 = 0.f, r1 = 0.f;
#pragma unroll
    for (int w = 0; w < 8; w++) {
        r0 += sacc[w][a0];
        r1 += sacc[w][a0 + 1];
    }
    float* cp = &g_cpart[((size_t)chunk * B_ + b) * A_];
    cp[a0]     = r0;
    cp[a0 + 1] = r1;
    if (tid == 0) {
        float s = 0.f;
#pragma unroll
        for (int i = 0; i < 8; i++) s += wred[i];
        g_epartA[((size_t)b * LQ + step) * NCK + chunk] = s;
    }
}

// ---------------- post-loop: all ws at once ----------------
__global__ void __launch_bounds__(256) ws_kernel(const int* __restrict__ enc_len,
                                                 float* __restrict__ out_ws) {
    int m = blockIdx.x;
    int b = m / LQ;
    int len = enc_len[b];
    __shared__ float sinv;
    if (threadIdx.x == 0) {
        float s = 0.f;
#pragma unroll
        for (int i = 0; i < NCK; i++) s += g_epartA[(size_t)m * NCK + i];
        sinv = 1.f / s;
    }
    __syncthreads();
    float inv = sinv;
    const float* ue = &g_ueA[(size_t)m * T_];
    float* wrow = &out_ws[(size_t)m * T_];
    for (int t = threadIdx.x; t < T_; t += 256)
        wrow[t] = (t < len) ? ue[t] * inv : 0.f;
}

// ---------------- final context reduce (step 100 only) ----------------
__global__ void __launch_bounds__(512) final_c_kernel(int step) {
    int b = blockIdx.x, a = threadIdx.x;
    __shared__ float sinv;
    if (a == 0) {
        float s = 0.f;
#pragma unroll
        for (int i = 0; i < NCK; i++)
            s += g_epartA[((size_t)b * LQ + step) * NCK + i];
        sinv = 1.f / s;
    }
    __syncthreads();
    float s = 0.f;
#pragma unroll
    for (int tc = 0; tc < NCK; tc++) s += g_cpart[((size_t)tc * B_ + b) * A_ + a];
    g_zcH[((size_t)b * LQ + step) * 1024 + 512 + a] = __float2half_rn(s * sinv);
}

// ---------------- final epilogue: log_softmax gather + argmax ----------------
__global__ void __launch_bounds__(256) epilogue_kernel(const int* __restrict__ ys,
                                                       const float* __restrict__ logits,
                                                       float* __restrict__ out_ylp,
                                                       float* __restrict__ out_pred) {
    int m = blockIdx.x, tid = threadIdx.x;
    const float* row = logits + (size_t)m * V_;
    __shared__ float sv[256];
    __shared__ int si[256];
    float mx = -3.4e38f; int mi = 0;
    for (int v = tid; v < V_; v += 256) {
        float x = row[v];
        if (x > mx) { mx = x; mi = v; }
    }
    sv[tid] = mx; si[tid] = mi; __syncthreads();
    for (int off = 128; off; off >>= 1) {
        if (tid < off) {
            float xo = sv[tid + off]; int io = si[tid + off];
            if (xo > sv[tid] || (xo == sv[tid] && io < si[tid])) { sv[tid] = xo; si[tid] = io; }
        }
        __syncthreads();
    }
    mx = sv[0]; int argi = si[0]; __syncthreads();
    float s = 0.f;
    for (int v = tid; v < V_; v += 256) s += __expf(row[v] - mx);
    sv[tid] = s; __syncthreads();
    for (int off = 128; off; off >>= 1) {
        if (tid < off) sv[tid] += sv[tid + off];
        __syncthreads();
    }
    if (tid == 0) {
        int b = m / LQ, t = m % LQ;
        int yo = (t < 100) ? ys[b * 100 + t] : 2;   // EOS=2
        out_ylp[m]  = row[yo] - mx - logf(sv[0]);
        out_pred[m] = (float)argi;
    }
}

// ---------------- host launch ----------------
extern "C" void kernel_launch(void* const* d_in, const int* in_sizes, int n_in,
                              void* d_out, int out_size) {
    const float* enc_pad  = (const float*)d_in[0];
    const int*   enc_len  = (const int*)  d_in[1];
    const int*   ys       = (const int*)  d_in[2];
    const float* emb_tab  = (const float*)d_in[3];
    const float* W_ih     = (const float*)d_in[4];
    const float* W_hh     = (const float*)d_in[5];
    const float* b_ih     = (const float*)d_in[6];
    const float* b_hh     = (const float*)d_in[7];
    const float* W_enc    = (const float*)d_in[8];
    const float* W_dec    = (const float*)d_in[9];
    const float* v_att    = (const float*)d_in[10];
    const float* W_out    = (const float*)d_in[11];
    const float* b_out    = (const float*)d_in[12];
    (void)in_sizes; (void)n_in;

    float* out = (float*)d_out;
    const size_t n_logits = (size_t)B_ * LQ * V_;
    const size_t n_row    = (size_t)B_ * LQ;
    const size_t n_full   = n_logits + 2 * n_row + (size_t)B_ * LQ * T_;
    bool full = ((size_t)out_size >= n_full);

    float* out_logits = out;
    float* out_ylp  = full ? out + n_logits            : nullptr;
    float* out_pred = full ? out + n_logits + n_row    : nullptr;
    float* out_ws   = full ? out + n_logits + 2*n_row  : nullptr;

    float *pEmbG, *pBias;
    __half *pPX, *pWencHT, *pZcH, *pWoutH, *pEmbH, *pWihH;
    cudaGetSymbolAddress((void**)&pPX,     g_PX);
    cudaGetSymbolAddress((void**)&pWencHT, g_WencHT);
    cudaGetSymbolAddress((void**)&pZcH,    g_zcH);
    cudaGetSymbolAddress((void**)&pWoutH,  g_WoutH);
    cudaGetSymbolAddress((void**)&pEmbH,   g_embH);
    cudaGetSymbolAddress((void**)&pWihH,   g_WihH);
    cudaGetSymbolAddress((void**)&pEmbG,   g_embg);
    cudaGetSymbolAddress((void**)&pBias,   g_bias);

    // setup
    init_state_kernel<<<(NCK * B_ * A_ + 255) / 256, 256>>>();
    convert_enc_kernel<<<(B_ * T_ * A_ / 2 + 255) / 256, 256>>>(enc_pad);
    transpose_wenc_h_kernel<<<(512 * 512 + 255) / 256, 256>>>(W_enc, W_dec);
    convert_wout_kernel<<<(int)(((size_t)NPAD * 1024 + 255) / 256), 256>>>(W_out);
    pack_wrec_kernel<<<(G4H * 1024 + 255) / 256, 256>>>(W_ih, W_hh, b_ih, b_hh);
    gather_emb_kernel<<<B_ * LQ, 128>>>(ys, emb_tab);

    // enc_proj: X(fp16, strided in g_PX) @ W_enc(fp16) -> P half of g_PX (ldc=1024)
    {
        dim3 g(A_ / 128, (B_ * T_) / 128);   // (4, 375)
        hgemm_nt<__half><<<g, 256>>>(pPX + 512, 1024, pWencHT, A_, nullptr,
                                     pPX, 1024, B_ * T_, A_, A_);
    }
    // emb-part of gates (+combined bias), HMMA fp16 inputs, fp32 out
    {
        dim3 g(G4H / 128, MPAD / 128);       // (16, 26)
        hgemm_nt<float><<<g, 256>>>(pEmbH, 512, pWihH, 512, pBias, pEmbG, G4H,
                                    B_ * LQ, G4H, 512);
    }

    // sequential decode loop (3 kernels/step)
    for (int t = 0; t < LQ; t++) {
        gates_kernel<<<dim3(16, 8), 256>>>(t);
        lstm_pw_q_kernel<<<B_, 1024>>>(t);
        attn_ctx_kernel<<<dim3(NCK, B_), 256>>>(enc_len, v_att, t);
    }
    final_c_kernel<<<B_, 512>>>(LQ - 1);
    if (full) {
        ws_kernel<<<B_ * LQ, 256>>>(enc_len, out_ws);
    }

    // logits = zc(fp16) @ W_out(fp16)^T + b_out, tensor cores, fp32 out
    {
        dim3 g(NPAD / 128, MPAD / 128);      // (79, 26)
        hgemm_nt<float><<<g, 256>>>(pZcH, 1024, pWoutH, 1024, b_out, out_logits, V_,
                                    B_ * LQ, V_, 1024);
    }
    if (full) {
        epilogue_kernel<<<B_ * LQ, 256>>>(ys, out_logits, out_ylp, out_pred);
    }
}

// round 16
// speedup vs baseline: 1.0387x; 1.0387x over previous
#include <cuda_runtime.h>
#include <cuda_fp16.h>
#include <cstdint>
#include <cstddef>

#define DEV_INLINE __device__ __forceinline__

constexpr int B_  = 32;
constexpr int T_  = 1500;
constexpr int A_  = 512;
constexpr int E_  = 512;
constexpr int H_  = 512;
constexpr int V_  = 10000;
constexpr int LQ  = 101;    // L+1
constexpr int G4H = 2048;   // 4*H
constexpr int NCK = 12;     // fused attn/context T-chunks (strided assignment)
constexpr int MPAD = 3328;  // 26*128 (rows padded)
constexpr int NPAD = 10112; // 79*128 (vocab padded)

// ---------------- device scratch (static, allowed) ----------------
__device__ __half g_Ph[(size_t)B_ * T_ * A_];        // enc_proj in fp16 (49 MB)
__device__ __half g_encH[(size_t)B_ * T_ * A_];      // enc_pad in fp16 (49 MB)
__device__ __half g_embH[(size_t)MPAD * E_];         // gathered embeddings fp16, padded
__device__ __half g_WihH[(size_t)G4H * 512];         // W_ih[:, :512] fp16
__device__ float g_embg[(size_t)B_ * LQ * G4H];      // emb-part of gates + bias
__device__ __half g_zcH[(size_t)MPAD * 1024];        // [dec_z | c] fp16, padded (pad rows stay 0)
__device__ __half g_WoutH[(size_t)NPAD * 1024];      // W_out fp16, padded
__device__ __half g_WencHT[A_ * A_];                 // W_enc^T in fp16
__device__ __half g_WdecH[(size_t)H_ * A_];          // W_dec fp16 [k][j]
__device__ __half g_WrecH[(size_t)G4H * 1024];       // [W_ih(:,512:1024) | W_hh] fp16
__device__ float g_bias[G4H];                        // b_ih + b_hh
__device__ float g_decz[B_ * H_];
__device__ float g_decc[B_ * H_];
__device__ float g_q[B_ * A_];
__device__ float g_gpart[8 * B_ * G4H];              // split-K partials of gates
__device__ float g_ueA[(size_t)B_ * LQ * T_];        // exp(e) for ALL steps (19.4 MB)
__device__ float g_epartA[(size_t)B_ * LQ * NCK];    // per-chunk ue sums, all steps
__device__ float g_cpart[(size_t)NCK * B_ * A_];     // UNNORMALIZED context partials

// ---------------- helpers ----------------
DEV_INLINE unsigned long long pack2(float x, float y) {
    unsigned long long r;
    asm("mov.b64 %0, {%1, %2};" : "=l"(r) : "f"(x), "f"(y));
    return r;
}
DEV_INLINE void ffma2(unsigned long long& acc, unsigned long long a2, unsigned long long b2) {
    asm("fma.rn.f32x2 %0, %1, %2, %0;" : "+l"(acc) : "l"(a2), "l"(b2));
}
DEV_INLINE float lo32(unsigned long long v) { return __uint_as_float((unsigned)(v & 0xffffffffull)); }
DEV_INLINE float hi32(unsigned long long v) { return __uint_as_float((unsigned)(v >> 32)); }

DEV_INLINE float tanh_mufu(float x) {
    float y;
    asm("tanh.approx.f32 %0, %1;" : "=f"(y) : "f"(x));
    return y;
}
DEV_INLINE float sig_acc(float x) { return 1.f / (1.f + expf(-x)); }

DEV_INLINE void stcs_f(float* p, float v) {
    asm volatile("st.global.cs.f32 [%0], %1;" :: "l"(p), "f"(v) : "memory");
}

#define LDMATRIX_X4(R0, R1, R2, R3, addr)                                      \
    asm volatile("ldmatrix.sync.aligned.m8n8.x4.shared.b16 {%0,%1,%2,%3}, [%4];" \
                 : "=r"(R0), "=r"(R1), "=r"(R2), "=r"(R3) : "r"(addr))

#define MMA16816(d, a, b)                                                      \
    asm volatile("mma.sync.aligned.m16n8k16.row.col.f32.f16.f16.f32 "          \
                 "{%0,%1,%2,%3}, {%4,%5,%6,%7}, {%8,%9}, {%0,%1,%2,%3};"       \
                 : "+f"(d[0]), "+f"(d[1]), "+f"(d[2]), "+f"(d[3])              \
                 : "r"(a[0]), "r"(a[1]), "r"(a[2]), "r"(a[3]),                 \
                   "r"(b[0]), "r"(b[1]))

// ---------------- setup kernels ----------------
__global__ void init_state_kernel() {
    int i = blockIdx.x * blockDim.x + threadIdx.x;
    if (i < B_ * H_) { g_decz[i] = 0.f; g_decc[i] = 0.f; }
    if (i < NCK * B_ * A_) g_cpart[i] = 0.f;
}

__global__ void convert_enc_kernel(const float* __restrict__ enc) {
    size_t i = (size_t)blockIdx.x * blockDim.x + threadIdx.x;
    size_t n2 = (size_t)B_ * T_ * A_ / 2;
    if (i < n2) {
        float2 f = ((const float2*)enc)[i];
        ((__half2*)g_encH)[i] = __floats2half2_rn(f.x, f.y);
    }
}

__global__ void transpose_wenc_h_kernel(const float* __restrict__ We,
                                        const float* __restrict__ Wd) {
    int idx = blockIdx.x * 256 + threadIdx.x;
    if (idx < 512 * 512) {
        int d = idx >> 9, a = idx & 511;
        g_WencHT[a * 512 + d] = __float2half_rn(We[idx]);
        g_WdecH[idx] = __float2half_rn(Wd[idx]);
    }
}

__global__ void convert_wout_kernel(const float* __restrict__ W_out) {
    size_t idx = (size_t)blockIdx.x * 256 + threadIdx.x;
    if (idx < (size_t)NPAD * 1024) {
        int n = (int)(idx >> 10), k = (int)(idx & 1023);
        g_WoutH[idx] = (n < V_) ? __float2half_rn(W_out[(size_t)n * 1024 + k]) : __half(0);
    }
}

__global__ void pack_wrec_kernel(const float* __restrict__ W_ih, const float* __restrict__ W_hh,
                                 const float* __restrict__ b_ih, const float* __restrict__ b_hh) {
    int idx = blockIdx.x * 256 + threadIdx.x;
    if (idx < G4H * 1024) {
        int j = idx >> 10, k = idx & 1023;
        float v = (k < 512) ? W_ih[(size_t)j * 1024 + 512 + k]
                            : W_hh[(size_t)j * 512 + (k - 512)];
        g_WrecH[idx] = __float2half_rn(v);
    }
    if (idx < G4H * 512) {
        int j = idx >> 9, k = idx & 511;
        g_WihH[idx] = __float2half_rn(W_ih[(size_t)j * 1024 + k]);
    }
    if (idx < G4H) g_bias[idx] = b_ih[idx] + b_hh[idx];
}

__global__ void gather_emb_kernel(const int* __restrict__ ys, const float* __restrict__ emb) {
    int m = blockIdx.x;
    int b = m / LQ, t = m % LQ;
    int idx = (t == 0) ? 1 : ys[b * 100 + t - 1];   // BOS=1
    const float* src = &emb[(size_t)idx * 512];
    __half* dst = &g_embH[(size_t)m * 512];
    for (int k = threadIdx.x; k < 512; k += 128) dst[k] = __float2half_rn(src[k]);
}

// ---------------- HMMA tensor-core NT GEMM ----------------
DEV_INLINE void store_out(float* p, float v) { *p = v; }
DEV_INLINE void store_out(__half* p, float v) { *p = __float2half_rn(v); }

template <typename OutT>
__global__ void __launch_bounds__(256) hgemm_nt(
    const __half* __restrict__ A, int lda,
    const __half* __restrict__ Bm, int ldb,
    const float* __restrict__ bias,
    OutT* __restrict__ C, int ldc,
    int M, int N, int K)
{
    __shared__ __half As[2][128][40];
    __shared__ __half Bs[2][128][40];

    const int tid = threadIdx.x;
    const int row0 = blockIdx.y * 128, col0 = blockIdx.x * 128;
    const int warp = tid >> 5, lane = tid & 31;
    const int wm = warp & 1, wn = warp >> 1;

    const int grow = tid >> 1;
    const int gcol = (tid & 1) * 16;
    const __half* a_src = A + (size_t)(row0 + grow) * lda + gcol;
    const __half* b_src = Bm + (size_t)(col0 + grow) * ldb + gcol;

    uint4 ar0, ar1, br0, br1;
    float acc[4][4][4];
#pragma unroll
    for (int i = 0; i < 4; i++)
#pragma unroll
        for (int j = 0; j < 4; j++) {
            acc[i][j][0] = 0.f; acc[i][j][1] = 0.f; acc[i][j][2] = 0.f; acc[i][j][3] = 0.f;
        }

#define LOADG(k0)                                                              \
    do {                                                                       \
        ar0 = *(const uint4*)(a_src + (k0));                                   \
        ar1 = *(const uint4*)(a_src + (k0) + 8);                               \
        br0 = *(const uint4*)(b_src + (k0));                                   \
        br1 = *(const uint4*)(b_src + (k0) + 8);                               \
    } while (0)

#define STORES(buf)                                                            \
    do {                                                                       \
        *(uint4*)&As[buf][grow][gcol]     = ar0;                               \
        *(uint4*)&As[buf][grow][gcol + 8] = ar1;                               \
        *(uint4*)&Bs[buf][grow][gcol]     = br0;                               \
        *(uint4*)&Bs[buf][grow][gcol + 8] = br1;                               \
    } while (0)

    const int ntiles = K >> 5;
    LOADG(0);
    STORES(0);
    if (ntiles > 1) LOADG(32);
    __syncthreads();

    const int a_row = wm * 64 + (lane & 15);
    const int a_kof = (lane >> 4) * 8;
    const int b_rof = (lane & 7) + ((lane >> 4) & 1) * 8;
    const int b_kof = ((lane >> 3) & 1) * 8;

    for (int kt = 0; kt < ntiles; kt++) {
        const int cur = kt & 1;
#pragma unroll
        for (int ks = 0; ks < 2; ks++) {
            const int kc = ks * 16;
            uint32_t a_frag[4][4];
            uint32_t b_frag[4][2];
#pragma unroll
            for (int mi = 0; mi < 4; mi++) {
                uint32_t addr = (uint32_t)__cvta_generic_to_shared(
                    &As[cur][a_row + mi * 16][kc + a_kof]);
                LDMATRIX_X4(a_frag[mi][0], a_frag[mi][1], a_frag[mi][2], a_frag[mi][3], addr);
            }
#pragma unroll
            for (int p = 0; p < 2; p++) {
                uint32_t r0, r1, r2, r3;
                uint32_t addr = (uint32_t)__cvta_generic_to_shared(
                    &Bs[cur][wn * 32 + p * 16 + b_rof][kc + b_kof]);
                LDMATRIX_X4(r0, r1, r2, r3, addr);
                b_frag[p * 2][0] = r0;     b_frag[p * 2][1] = r1;
                b_frag[p * 2 + 1][0] = r2; b_frag[p * 2 + 1][1] = r3;
            }
#pragma unroll
            for (int mi = 0; mi < 4; mi++) {
#pragma unroll
                for (int nj = 0; nj < 4; nj++) {
                    MMA16816(acc[mi][nj], a_frag[mi], b_frag[nj]);
                }
            }
        }
        if (kt + 1 < ntiles) {
            STORES((kt + 1) & 1);
            if (kt + 2 < ntiles) LOADG((kt + 2) * 32);
        }
        __syncthreads();
    }
#undef LOADG
#undef STORES

#pragma unroll
    for (int mi = 0; mi < 4; mi++) {
        int r = row0 + wm * 64 + mi * 16 + (lane >> 2);
#pragma unroll
        for (int nj = 0; nj < 4; nj++) {
            int c = col0 + wn * 32 + nj * 8 + (lane & 3) * 2;
            float b0 = (bias && c < N)     ? bias[c]     : 0.f;
            float b1 = (bias && c + 1 < N) ? bias[c + 1] : 0.f;
            if (r < M) {
                OutT* crow = C + (size_t)r * ldc;
                if (c < N)     store_out(crow + c,     acc[mi][nj][0] + b0);
                if (c + 1 < N) store_out(crow + c + 1, acc[mi][nj][1] + b1);
            }
            if (r + 8 < M) {
                OutT* crow = C + (size_t)(r + 8) * ldc;
                if (c < N)     store_out(crow + c,     acc[mi][nj][2] + b0);
                if (c + 1 < N) store_out(crow + c + 1, acc[mi][nj][3] + b1);
            }
        }
    }
}

// ---------------- per-step recurrent gates (split-K, fp16 Wrec) ----------
__global__ void __launch_bounds__(256) gates_kernel(int step) {
    __shared__ float xh_s[32][36];
    __shared__ float w_s[32][132];
    __shared__ float inv_s[32];
    int tid = threadIdx.x;
    int j0 = blockIdx.x * 128;
    int kz = blockIdx.y;
    int bq = tid & 7;
    int jq = tid >> 3;

    if (tid < 32) {
        float iv = 1.f;
        if (step > 0) {
            float s = 0.f;
#pragma unroll
            for (int i = 0; i < NCK; i++)
                s += g_epartA[((size_t)tid * LQ + step - 1) * NCK + i];
            iv = 1.f / s;
        }
        inv_s[tid] = iv;
    }
    __syncthreads();

    unsigned long long acc[4][2];
#pragma unroll
    for (int i = 0; i < 4; i++) { acc[i][0] = 0ull; acc[i][1] = 0ull; }

    for (int kt0 = 0; kt0 < 128; kt0 += 32) {
        int kb = kz * 128 + kt0;
#pragma unroll
        for (int r = 0; r < 4; r++) {
            int lin = tid + r * 256;
            int kt = lin & 31, b = lin >> 5;
            int kk = kb + kt;
            float v;
            if (kk < 512) {
                v = 0.f;
#pragma unroll
                for (int tc = 0; tc < NCK; tc++)
                    v += g_cpart[((size_t)tc * B_ + b) * A_ + kk];
                v *= inv_s[b];
                if (blockIdx.x == 0 && step > 0)
                    g_zcH[((size_t)b * LQ + step - 1) * 1024 + 512 + kk] = __float2half_rn(v);
            } else {
                v = g_decz[b * 512 + kk - 512];
            }
            xh_s[kt][b] = v;
        }
        {
            int jj = tid >> 1, kof = (tid & 1) * 16;
            const __half* wp = &g_WrecH[(size_t)(j0 + jj) * 1024 + kb + kof];
            uint4 h0 = *(const uint4*)wp;
            uint4 h1 = *(const uint4*)(wp + 8);
            const __half2* p0 = (const __half2*)&h0;
            const __half2* p1 = (const __half2*)&h1;
#pragma unroll
            for (int q = 0; q < 4; q++) {
                float2 f = __half22float2(p0[q]);
                w_s[kof + 2 * q][jj]     = f.x;
                w_s[kof + 2 * q + 1][jj] = f.y;
            }
#pragma unroll
            for (int q = 0; q < 4; q++) {
                float2 f = __half22float2(p1[q]);
                w_s[kof + 8 + 2 * q][jj]     = f.x;
                w_s[kof + 8 + 2 * q + 1][jj] = f.y;
            }
        }
        __syncthreads();
#pragma unroll
        for (int kt = 0; kt < 32; kt++) {
            float4 av = *(const float4*)&xh_s[kt][bq * 4];
            float4 wv = *(const float4*)&w_s[kt][jq * 4];
            unsigned long long w2a = pack2(wv.x, wv.y);
            unsigned long long w2b = pack2(wv.z, wv.w);
            unsigned long long a2;
            a2 = pack2(av.x, av.x); ffma2(acc[0][0], a2, w2a); ffma2(acc[0][1], a2, w2b);
            a2 = pack2(av.y, av.y); ffma2(acc[1][0], a2, w2a); ffma2(acc[1][1], a2, w2b);
            a2 = pack2(av.z, av.z); ffma2(acc[2][0], a2, w2a); ffma2(acc[2][1], a2, w2b);
            a2 = pack2(av.w, av.w); ffma2(acc[3][0], a2, w2a); ffma2(acc[3][1], a2, w2b);
        }
        __syncthreads();
    }
#pragma unroll
    for (int ib = 0; ib < 4; ib++) {
        int b = bq * 4 + ib;
        float* gp = &g_gpart[(size_t)kz * (B_ * G4H) + (size_t)b * G4H + j0 + jq * 4];
        gp[0] = lo32(acc[ib][0]); gp[1] = hi32(acc[ib][0]);
        gp[2] = lo32(acc[ib][1]); gp[3] = hi32(acc[ib][1]);
    }
}

// ---------------- per-step LSTM pointwise + q GEMV (fp16 W_dec, 4-way) -----
__global__ void __launch_bounds__(1024) lstm_pw_q_kernel(int step) {
    int b = blockIdx.x;
    int tid = threadIdx.x;
    __shared__ float z_s[512];
    __shared__ float2 qp2[1024];

    if (tid < 512) {
        size_t m = (size_t)b * LQ + step;
        const float* eg = &g_embg[m * G4H];
        float gi = eg[tid], gf = eg[512 + tid], gg = eg[1024 + tid], go = eg[1536 + tid];
#pragma unroll
        for (int kz = 0; kz < 8; kz++) {
            const float* gp = &g_gpart[(size_t)kz * (B_ * G4H) + (size_t)b * G4H];
            gi += gp[tid]; gf += gp[512 + tid]; gg += gp[1024 + tid]; go += gp[1536 + tid];
        }
        float cp = g_decc[b * 512 + tid];
        float cn = sig_acc(gf) * cp + sig_acc(gi) * tanhf(gg);
        float z  = sig_acc(go) * tanhf(cn);
        g_decc[b * 512 + tid] = cn;
        g_decz[b * 512 + tid] = z;
        g_zcH[m * 1024 + tid] = __float2half_rn(z);
        z_s[tid] = z;
    }
    __syncthreads();

    int jp = tid & 255;
    int k0 = tid >> 8;
    const __half2* wdh = (const __half2*)g_WdecH;
    float qx = 0.f, qy = 0.f;
#pragma unroll 8
    for (int k = 0; k < 128; k++) {
        int kk = k0 * 128 + k;
        float2 w = __half22float2(wdh[(size_t)kk * 256 + jp]);
        float zk = z_s[kk];
        qx += zk * w.x;
        qy += zk * w.y;
    }
    qp2[tid] = make_float2(qx, qy);
    __syncthreads();
    if (tid < 256) {
        float2 a = qp2[tid], b2 = qp2[tid + 256], c = qp2[tid + 512], d = qp2[tid + 768];
        g_q[b * 512 + 2 * tid]     = (a.x + b2.x) + (c.x + d.x);
        g_q[b * 512 + 2 * tid + 1] = (a.y + b2.y) + (c.y + d.y);
    }
}

// ---------------- per-step FUSED attention scores + context (strided t) ----
__global__ void __launch_bounds__(256) attn_ctx_kernel(const int* __restrict__ enc_len,
                                                       const float* __restrict__ v_att,
                                                       int step) {
    int b = blockIdx.y, chunk = blockIdx.x;
    int len = enc_len[b];
    int tid = threadIdx.x, warp = tid >> 5, lane = tid & 31;
    __shared__ float sacc[8][512];
    __shared__ float wred[8];

    float qv[16], vv[16];
    {
        const float* qb = &g_q[b * 512 + lane * 8];
        *(float4*)&qv[0]  = *(const float4*)(qb);
        *(float4*)&qv[4]  = *(const float4*)(qb + 4);
        *(float4*)&qv[8]  = *(const float4*)(qb + 256);
        *(float4*)&qv[12] = *(const float4*)(qb + 260);
        const float* vb = &v_att[lane * 8];
        *(float4*)&vv[0]  = *(const float4*)(vb);
        *(float4*)&vv[4]  = *(const float4*)(vb + 4);
        *(float4*)&vv[8]  = *(const float4*)(vb + 256);
        *(float4*)&vv[12] = *(const float4*)(vb + 260);
    }
    float acc[16];
#pragma unroll
    for (int i = 0; i < 16; i++) acc[i] = 0.f;

    const int iw = warp * 16;
    float wsum = 0.f;
    float* uerow = &g_ueA[((size_t)b * LQ + step) * T_];
    const __half* Pb = &g_Ph[(size_t)b * T_ * 512];
    const __half* Xb = &g_encH[(size_t)b * T_ * 512];

#pragma unroll 1
    for (int r = 0; r < 16; r += 2) {
        int t0 = chunk + 12 * (iw + r);
        if (t0 >= len) break;
        int t1 = t0 + 12;
        bool m1 = (t1 < len);
        uint4 z4 = make_uint4(0, 0, 0, 0);
        const __half* P0 = Pb + (size_t)t0 * 512;
        const __half* P1 = Pb + (size_t)t1 * 512;
        const __half* X0 = Xb + (size_t)t0 * 512;
        const __half* X1 = Xb + (size_t)t1 * 512;
        uint4 u0a = __ldcs((const uint4*)(P0 + lane * 8));
        uint4 u0b = __ldcs((const uint4*)(P0 + 256 + lane * 8));
        uint4 u1a = m1 ? __ldcs((const uint4*)(P1 + lane * 8))       : z4;
        uint4 u1b = m1 ? __ldcs((const uint4*)(P1 + 256 + lane * 8)) : z4;
        uint4 x0a = __ldcs((const uint4*)(X0 + lane * 8));
        uint4 x0b = __ldcs((const uint4*)(X0 + 256 + lane * 8));
        uint4 x1a = m1 ? __ldcs((const uint4*)(X1 + lane * 8))       : z4;
        uint4 x1b = m1 ? __ldcs((const uint4*)(X1 + 256 + lane * 8)) : z4;

        float s0 = 0.f, s1 = 0.f;
        {
            const __half2* h0a = (const __half2*)&u0a;
            const __half2* h0b = (const __half2*)&u0b;
            const __half2* h1a = (const __half2*)&u1a;
            const __half2* h1b = (const __half2*)&u1b;
#pragma unroll
            for (int j = 0; j < 4; j++) {
                float2 f0 = __half22float2(h0a[j]);
                float2 f1 = __half22float2(h1a[j]);
                s0 += vv[2*j]   * tanh_mufu(f0.x + qv[2*j]);
                s0 += vv[2*j+1] * tanh_mufu(f0.y + qv[2*j+1]);
                s1 += vv[2*j]   * tanh_mufu(f1.x + qv[2*j]);
                s1 += vv[2*j+1] * tanh_mufu(f1.y + qv[2*j+1]);
            }
#pragma unroll
            for (int j = 0; j < 4; j++) {
                float2 f0 = __half22float2(h0b[j]);
                float2 f1 = __half22float2(h1b[j]);
                s0 += vv[8+2*j]   * tanh_mufu(f0.x + qv[8+2*j]);
                s0 += vv[8+2*j+1] * tanh_mufu(f0.y + qv[8+2*j+1]);
                s1 += vv[8+2*j]   * tanh_mufu(f1.x + qv[8+2*j]);
                s1 += vv[8+2*j+1] * tanh_mufu(f1.y + qv[8+2*j+1]);
            }
        }
#pragma unroll
        for (int off = 16; off; off >>= 1) {
            s0 += __shfl_xor_sync(0xffffffffu, s0, off);
            s1 += __shfl_xor_sync(0xffffffffu, s1, off);
        }
        float ue0 = __expf(s0);
        float ue1 = m1 ? __expf(s1) : 0.f;
        if (lane == 0) {
            stcs_f(uerow + t0, ue0);
            if (m1) stcs_f(uerow + t1, ue1);
        }
        wsum += ue0 + ue1;
        {
            const __half2* g0a = (const __half2*)&x0a;
            const __half2* g0b = (const __half2*)&x0b;
            const __half2* g1a = (const __half2*)&x1a;
            const __half2* g1b = (const __half2*)&x1b;
#pragma unroll
            for (int j = 0; j < 4; j++) {
                float2 f0 = __half22float2(g0a[j]);
                float2 f1 = __half22float2(g1a[j]);
                acc[2*j]   += ue0 * f0.x + ue1 * f1.x;
                acc[2*j+1] += ue0 * f0.y + ue1 * f1.y;
            }
#pragma unroll
            for (int j = 0; j < 4; j++) {
                float2 f0 = __half22float2(g0b[j]);
                float2 f1 = __half22float2(g1b[j]);
                acc[8+2*j]   += ue0 * f0.x + ue1 * f1.x;
                acc[8+2*j+1] += ue0 * f0.y + ue1 * f1.y;
            }
        }
    }

#pragma unroll
    for (int i = 0; i < 8; i++) {
        sacc[warp][lane * 8 + i]       = acc[i];
        sacc[warp][256 + lane * 8 + i] = acc[8 + i];
    }
    if (lane == 0) wred[warp] = wsum;
    __syncthreads();

    int a0 = tid * 2;
    float r0 = 0.f, r1 = 0.f;
#pragma unroll
    for (int w = 0; w < 8; w++) {
        r0 += sacc[w][a0];
        r1 += sacc[w][a0 + 1];
    }
    float* cp = &g_cpart[((size_t)chunk * B_ + b) * A_];
    cp[a0]     = r0;
    cp[a0 + 1] = r1;
    if (tid == 0) {
        float s = 0.f;
#pragma unroll
        for (int i = 0; i < 8; i++) s += wred[i];
        g_epartA[((size_t)b * LQ + step) * NCK + chunk] = s;
    }
}

// ---------------- post-loop: all ws at once ----------------
__global__ void __launch_bounds__(256) ws_kernel(const int* __restrict__ enc_len,
                                                 float* __restrict__ out_ws) {
    int m = blockIdx.x;
    int b = m / LQ;
    int len = enc_len[b];
    __shared__ float sinv;
    if (threadIdx.x == 0) {
        float s = 0.f;
#pragma unroll
        for (int i = 0; i < NCK; i++) s += g_epartA[(size_t)m * NCK + i];
        sinv = 1.f / s;
    }
    __syncthreads();
    float inv = sinv;
    const float* ue = &g_ueA[(size_t)m * T_];
    float* wrow = &out_ws[(size_t)m * T_];
    for (int t = threadIdx.x; t < T_; t += 256)
        wrow[t] = (t < len) ? ue[t] * inv : 0.f;
}

// ---------------- final context reduce (step 100 only) ----------------
__global__ void __launch_bounds__(512) final_c_kernel(int step) {
    int b = blockIdx.x, a = threadIdx.x;
    __shared__ float sinv;
    if (a == 0) {
        float s = 0.f;
#pragma unroll
        for (int i = 0; i < NCK; i++)
            s += g_epartA[((size_t)b * LQ + step) * NCK + i];
        sinv = 1.f / s;
    }
    __syncthreads();
    float s = 0.f;
#pragma unroll
    for (int tc = 0; tc < NCK; tc++) s += g_cpart[((size_t)tc * B_ + b) * A_ + a];
    g_zcH[((size_t)b * LQ + step) * 1024 + 512 + a] = __float2half_rn(s * sinv);
}

// ---------------- final epilogue: log_softmax gather + argmax ----------------
__global__ void __launch_bounds__(256) epilogue_kernel(const int* __restrict__ ys,
                                                       const float* __restrict__ logits,
                                                       float* __restrict__ out_ylp,
                                                       float* __restrict__ out_pred) {
    int m = blockIdx.x, tid = threadIdx.x;
    const float* row = logits + (size_t)m * V_;
    __shared__ float sv[256];
    __shared__ int si[256];
    float mx = -3.4e38f; int mi = 0;
    for (int v = tid; v < V_; v += 256) {
        float x = row[v];
        if (x > mx) { mx = x; mi = v; }
    }
    sv[tid] = mx; si[tid] = mi; __syncthreads();
    for (int off = 128; off; off >>= 1) {
        if (tid < off) {
            float xo = sv[tid + off]; int io = si[tid + off];
            if (xo > sv[tid] || (xo == sv[tid] && io < si[tid])) { sv[tid] = xo; si[tid] = io; }
        }
        __syncthreads();
    }
    mx = sv[0]; int argi = si[0]; __syncthreads();
    float s = 0.f;
    for (int v = tid; v < V_; v += 256) s += __expf(row[v] - mx);
    sv[tid] = s; __syncthreads();
    for (int off = 128; off; off >>= 1) {
        if (tid < off) sv[tid] += sv[tid + off];
        __syncthreads();
    }
    if (tid == 0) {
        int b = m / LQ, t = m % LQ;
        int yo = (t < 100) ? ys[b * 100 + t] : 2;   // EOS=2
        out_ylp[m]  = row[yo] - mx - logf(sv[0]);
        out_pred[m] = (float)argi;
    }
}

// ---------------- host launch ----------------
extern "C" void kernel_launch(void* const* d_in, const int* in_sizes, int n_in,
                              void* d_out, int out_size) {
    const float* enc_pad  = (const float*)d_in[0];
    const int*   enc_len  = (const int*)  d_in[1];
    const int*   ys       = (const int*)  d_in[2];
    const float* emb_tab  = (const float*)d_in[3];
    const float* W_ih     = (const float*)d_in[4];
    const float* W_hh     = (const float*)d_in[5];
    const float* b_ih     = (const float*)d_in[6];
    const float* b_hh     = (const float*)d_in[7];
    const float* W_enc    = (const float*)d_in[8];
    const float* W_dec    = (const float*)d_in[9];
    const float* v_att    = (const float*)d_in[10];
    const float* W_out    = (const float*)d_in[11];
    const float* b_out    = (const float*)d_in[12];
    (void)in_sizes; (void)n_in;

    float* out = (float*)d_out;
    const size_t n_logits = (size_t)B_ * LQ * V_;
    const size_t n_row    = (size_t)B_ * LQ;
    const size_t n_full   = n_logits + 2 * n_row + (size_t)B_ * LQ * T_;
    bool full = ((size_t)out_size >= n_full);

    float* out_logits = out;
    float* out_ylp  = full ? out + n_logits            : nullptr;
    float* out_pred = full ? out + n_logits + n_row    : nullptr;
    float* out_ws   = full ? out + n_logits + 2*n_row  : nullptr;

    float *pEmbG, *pBias;
    __half *pPh, *pEncH, *pWencHT, *pZcH, *pWoutH, *pEmbH, *pWihH;
    cudaGetSymbolAddress((void**)&pPh,     g_Ph);
    cudaGetSymbolAddress((void**)&pEncH,   g_encH);
    cudaGetSymbolAddress((void**)&pWencHT, g_WencHT);
    cudaGetSymbolAddress((void**)&pZcH,    g_zcH);
    cudaGetSymbolAddress((void**)&pWoutH,  g_WoutH);
    cudaGetSymbolAddress((void**)&pEmbH,   g_embH);
    cudaGetSymbolAddress((void**)&pWihH,   g_WihH);
    cudaGetSymbolAddress((void**)&pEmbG,   g_embg);
    cudaGetSymbolAddress((void**)&pBias,   g_bias);

    // setup
    init_state_kernel<<<(NCK * B_ * A_ + 255) / 256, 256>>>();
    convert_enc_kernel<<<(B_ * T_ * A_ / 2 + 255) / 256, 256>>>(enc_pad);
    transpose_wenc_h_kernel<<<(512 * 512 + 255) / 256, 256>>>(W_enc, W_dec);
    convert_wout_kernel<<<(int)(((size_t)NPAD * 1024 + 255) / 256), 256>>>(W_out);
    pack_wrec_kernel<<<(G4H * 1024 + 255) / 256, 256>>>(W_ih, W_hh, b_ih, b_hh);
    gather_emb_kernel<<<B_ * LQ, 128>>>(ys, emb_tab);

    // enc_proj = enc_pad(fp16) @ W_enc(fp16) -> fp16, tensor cores
    {
        dim3 g(A_ / 128, (B_ * T_) / 128);   // (4, 375)
        hgemm_nt<__half><<<g, 256>>>(pEncH, A_, pWencHT, A_, nullptr, pPh, A_,
                                     B_ * T_, A_, A_);
    }
    // emb-part of gates (+combined bias), HMMA fp16 inputs, fp32 out
    {
        dim3 g(G4H / 128, MPAD / 128);       // (16, 26)
        hgemm_nt<float><<<g, 256>>>(pEmbH, 512, pWihH, 512, pBias, pEmbG, G4H,
                                    B_ * LQ, G4H, 512);
    }

    // sequential decode loop (3 kernels/step)
    for (int t = 0; t < LQ; t++) {
        gates_kernel<<<dim3(16, 8), 256>>>(t);
        lstm_pw_q_kernel<<<B_, 1024>>>(t);
        attn_ctx_kernel<<<dim3(NCK, B_), 256>>>(enc_len, v_att, t);
    }
    final_c_kernel<<<B_, 512>>>(LQ - 1);
    if (full) {
        ws_kernel<<<B_ * LQ, 256>>>(enc_len, out_ws);
    }

    // logits = zc(fp16) @ W_out(fp16)^T + b_out, tensor cores, fp32 out
    {
        dim3 g(NPAD / 128, MPAD / 128);      // (79, 26)
        hgemm_nt<float><<<g, 256>>>(pZcH, 1024, pWoutH, 1024, b_out, out_logits, V_,
                                    B_ * LQ, V_, 1024);
    }
    if (full) {
        epilogue_kernel<<<B_ * LQ, 256>>>(ys, out_logits, out_ylp, out_pred);
    }
}